// round 2
// baseline (speedup 1.0000x reference)
#include <cuda_runtime.h>
#include <math.h>

#define B_   2
#define S_   2048
#define DM_  1024
#define H_   16
#define HD_  64
#define MTOT (B_*S_)

// Scratch (alloc-free rule: __device__ globals)
__device__ float g_Q[MTOT*DM_];
__device__ float g_K[MTOT*DM_];
__device__ float g_V[MTOT*DM_];
__device__ float g_attn[MTOT*DM_];
__device__ float g_x[MTOT*DM_];

// ---------------------------------------------------------------------------
// SGEMM (NT): C[m][n] = sum_k A[m][k]*W[n][k] + bias[n] (+ res[m][n])
// 128x128 tile, BK=8, 256 threads, 8x8 per thread.
// which: 0->g_Q, 1->g_K, 2->g_V (ADD_RES=false); ADD_RES=true -> g_x
// ---------------------------------------------------------------------------
template<bool ADD_RES>
__global__ __launch_bounds__(256)
void sgemm_nt(const float* __restrict__ A, const float* __restrict__ W,
              const float* __restrict__ bias, const float* __restrict__ res,
              int which, int Kdim)
{
    __shared__ float As[8][132];
    __shared__ float Bs[8][132];

    const float* Abase = (A == nullptr) ? (const float*)g_attn : A;
    float* C = ADD_RES ? g_x : (which == 0 ? g_Q : (which == 1 ? g_K : g_V));

    const int tid = threadIdx.x;
    const int m0 = blockIdx.y * 128;
    const int n0 = blockIdx.x * 128;

    const int lr = tid >> 1;          // 0..127
    const int lc = (tid & 1) << 2;    // 0 or 4
    const float* Ap = Abase + (size_t)(m0 + lr) * Kdim + lc;
    const float* Wp = W     + (size_t)(n0 + lr) * Kdim + lc;

    const int tx = tid & 15;
    const int ty = tid >> 4;

    float acc[8][8];
    #pragma unroll
    for (int i = 0; i < 8; i++)
        #pragma unroll
        for (int j = 0; j < 8; j++) acc[i][j] = 0.f;

    for (int k0 = 0; k0 < Kdim; k0 += 8) {
        float4 a4 = *(const float4*)(Ap + k0);
        float4 b4 = *(const float4*)(Wp + k0);
        __syncthreads();
        As[lc+0][lr] = a4.x; As[lc+1][lr] = a4.y; As[lc+2][lr] = a4.z; As[lc+3][lr] = a4.w;
        Bs[lc+0][lr] = b4.x; Bs[lc+1][lr] = b4.y; Bs[lc+2][lr] = b4.z; Bs[lc+3][lr] = b4.w;
        __syncthreads();
        #pragma unroll
        for (int kk = 0; kk < 8; kk++) {
            float a[8], b[8];
            *(float4*)&a[0] = *(const float4*)&As[kk][ty*4];
            *(float4*)&a[4] = *(const float4*)&As[kk][ty*4 + 64];
            *(float4*)&b[0] = *(const float4*)&Bs[kk][tx*4];
            *(float4*)&b[4] = *(const float4*)&Bs[kk][tx*4 + 64];
            #pragma unroll
            for (int i = 0; i < 8; i++)
                #pragma unroll
                for (int j = 0; j < 8; j++)
                    acc[i][j] = fmaf(a[i], b[j], acc[i][j]);
        }
    }

    #pragma unroll
    for (int i = 0; i < 8; i++) {
        int row = m0 + ty*4 + (i & 3) + ((i >= 4) ? 64 : 0);
        #pragma unroll
        for (int jj = 0; jj < 2; jj++) {
            int col = n0 + tx*4 + jj*64;
            float4 bs = *(const float4*)&bias[col];
            float4 v;
            v.x = acc[i][jj*4+0] + bs.x;
            v.y = acc[i][jj*4+1] + bs.y;
            v.z = acc[i][jj*4+2] + bs.z;
            v.w = acc[i][jj*4+3] + bs.w;
            if (ADD_RES) {
                float4 r4 = *(const float4*)&res[(size_t)row*DM_ + col];
                v.x += r4.x; v.y += r4.y; v.z += r4.z; v.w += r4.w;
            }
            *(float4*)&C[(size_t)row*DM_ + col] = v;
        }
    }
}

// ---------------------------------------------------------------------------
// Flash attention: one block = (b,h, 64 query rows); loops over 64-row KV tiles.
// Threads: 256 as 16x16, each owns a 4x4 S tile and 4x4 O tile.
// smem: Qs [64][64] (q-major), KP [64][64] (K d-major XOR-swizzled, reused as P),
//       Vs [64][64] (k-major). 48KB total.
// ---------------------------------------------------------------------------
__global__ __launch_bounds__(256)
void flash_attn(const int* __restrict__ mask)
{
    __shared__ float sm[3*64*64];
    float* Qs = sm;
    float* KP = sm + 64*64;
    float* Vs = sm + 2*64*64;

    const int tid = threadIdx.x;
    const int tx = tid & 15;
    const int ty = tid >> 4;
    const int qt = blockIdx.x;
    const int bh = blockIdx.y;
    const int b  = bh >> 4;
    const int h  = bh & 15;
    const int q0 = qt * 64;
    const float scale = 0.125f;  // 1/sqrt(64)

    // Load Q tile (pre-scaled). 1024 float4s, 4 per thread.
    {
        const float* src = g_Q + ((size_t)(b*S_ + q0))*DM_ + h*HD_;
        #pragma unroll
        for (int it = 0; it < 4; it++) {
            int idx = tid + it*256;
            int r  = idx >> 4;
            int c4 = idx & 15;
            float4 v = *(const float4*)(src + (size_t)r*DM_ + c4*4);
            v.x *= scale; v.y *= scale; v.z *= scale; v.w *= scale;
            *(float4*)&Qs[r*64 + c4*4] = v;
        }
    }

    float m_i[4], l_i[4], o[4][4];
    #pragma unroll
    for (int i = 0; i < 4; i++) {
        m_i[i] = -1e30f; l_i[i] = 0.f;
        #pragma unroll
        for (int j = 0; j < 4; j++) o[i][j] = 0.f;
    }

    const int* mbase = mask + (size_t)b * S_ * S_;

    for (int k0 = 0; k0 < S_; k0 += 64) {
        __syncthreads();  // previous iteration done reading KP/Vs
        // Load K (transposed + XOR swizzle) and V (natural)
        {
            const float* ksrc = g_K + ((size_t)(b*S_ + k0))*DM_ + h*HD_;
            const float* vsrc = g_V + ((size_t)(b*S_ + k0))*DM_ + h*HD_;
            #pragma unroll
            for (int it = 0; it < 4; it++) {
                int idx = tid + it*256;
                int kr = idx >> 4;
                int c4 = idx & 15;
                float4 kv = *(const float4*)(ksrc + (size_t)kr*DM_ + c4*4);
                int pcol_base = (((kr >> 2) ^ c4) << 2) | (kr & 3);
                KP[(c4*4+0)*64 + pcol_base] = kv.x;
                KP[(c4*4+1)*64 + pcol_base] = kv.y;
                KP[(c4*4+2)*64 + pcol_base] = kv.z;
                KP[(c4*4+3)*64 + pcol_base] = kv.w;
                float4 vv = *(const float4*)(vsrc + (size_t)kr*DM_ + c4*4);
                *(float4*)&Vs[kr*64 + c4*4] = vv;
            }
        }
        __syncthreads();

        // S = Q K^T  (reduction over d = 64)
        float s[4][4];
        #pragma unroll
        for (int i = 0; i < 4; i++)
            #pragma unroll
            for (int j = 0; j < 4; j++) s[i][j] = 0.f;

        #pragma unroll 8
        for (int kk = 0; kk < 64; kk++) {
            float a0 = Qs[(ty*4+0)*64 + kk];
            float a1 = Qs[(ty*4+1)*64 + kk];
            float a2 = Qs[(ty*4+2)*64 + kk];
            float a3 = Qs[(ty*4+3)*64 + kk];
            float4 b4 = *(const float4*)&KP[kk*64 + ((tx ^ (kk >> 2)) << 2)];
            float bb[4] = {b4.x, b4.y, b4.z, b4.w};
            #pragma unroll
            for (int j = 0; j < 4; j++) {
                s[0][j] = fmaf(a0, bb[j], s[0][j]);
                s[1][j] = fmaf(a1, bb[j], s[1][j]);
                s[2][j] = fmaf(a2, bb[j], s[2][j]);
                s[3][j] = fmaf(a3, bb[j], s[3][j]);
            }
        }

        // Mask
        #pragma unroll
        for (int i = 0; i < 4; i++) {
            int qr = q0 + ty*4 + i;
            const int* mp = mbase + (size_t)qr*S_ + k0 + tx*4;
            #pragma unroll
            for (int j = 0; j < 4; j++)
                if (mp[j] == 0) s[i][j] = -1e9f;
        }

        // Online softmax: row stats over the 16 tx lanes in this half-warp.
        #pragma unroll
        for (int i = 0; i < 4; i++) {
            float mx = fmaxf(fmaxf(s[i][0], s[i][1]), fmaxf(s[i][2], s[i][3]));
            #pragma unroll
            for (int off = 8; off > 0; off >>= 1)
                mx = fmaxf(mx, __shfl_xor_sync(0xffffffffu, mx, off));
            float m_new = fmaxf(m_i[i], mx);
            float alpha = __expf(m_i[i] - m_new);
            float lsum = 0.f;
            #pragma unroll
            for (int j = 0; j < 4; j++) {
                s[i][j] = __expf(s[i][j] - m_new);
                lsum += s[i][j];
            }
            #pragma unroll
            for (int off = 8; off > 0; off >>= 1)
                lsum += __shfl_xor_sync(0xffffffffu, lsum, off);
            l_i[i] = l_i[i]*alpha + lsum;
            m_i[i] = m_new;
            #pragma unroll
            for (int j = 0; j < 4; j++) o[i][j] *= alpha;
        }

        __syncthreads();  // everyone done reading KP as K
        // Write P into KP as [qr][kk]
        #pragma unroll
        for (int i = 0; i < 4; i++) {
            float4 pv = make_float4(s[i][0], s[i][1], s[i][2], s[i][3]);
            *(float4*)&KP[(ty*4+i)*64 + tx*4] = pv;
        }
        __syncthreads();

        // O += P V  (reduction over kv rows = 64)
        #pragma unroll 8
        for (int kk = 0; kk < 64; kk++) {
            float p0 = KP[(ty*4+0)*64 + kk];
            float p1 = KP[(ty*4+1)*64 + kk];
            float p2 = KP[(ty*4+2)*64 + kk];
            float p3 = KP[(ty*4+3)*64 + kk];
            float4 v4 = *(const float4*)&Vs[kk*64 + tx*4];
            float vv[4] = {v4.x, v4.y, v4.z, v4.w};
            #pragma unroll
            for (int j = 0; j < 4; j++) {
                o[0][j] = fmaf(p0, vv[j], o[0][j]);
                o[1][j] = fmaf(p1, vv[j], o[1][j]);
                o[2][j] = fmaf(p2, vv[j], o[2][j]);
                o[3][j] = fmaf(p3, vv[j], o[3][j]);
            }
        }
    }

    // Epilogue: O /= l, write [b, s, h*64+dd]
    #pragma unroll
    for (int i = 0; i < 4; i++) {
        float inv = 1.f / l_i[i];
        int qr = q0 + ty*4 + i;
        float4 v = make_float4(o[i][0]*inv, o[i][1]*inv, o[i][2]*inv, o[i][3]*inv);
        *(float4*)&g_attn[((size_t)(b*S_ + qr))*DM_ + h*HD_ + tx*4] = v;
    }
}

// ---------------------------------------------------------------------------
// LayerNorm: unbiased std (ddof=1), denominator (std + eps). One block per row.
// ---------------------------------------------------------------------------
__global__ __launch_bounds__(256)
void layernorm(const float* __restrict__ gamma, const float* __restrict__ beta,
               float* __restrict__ out)
{
    __shared__ float red[2][8];
    const int row = blockIdx.x;
    const int tid = threadIdx.x;
    const float* xr = g_x + (size_t)row * DM_;
    const int c = tid * 4;

    float4 xv = *(const float4*)(xr + c);
    float sum = xv.x + xv.y + xv.z + xv.w;
    float sq  = xv.x*xv.x + xv.y*xv.y + xv.z*xv.z + xv.w*xv.w;

    #pragma unroll
    for (int off = 16; off > 0; off >>= 1) {
        sum += __shfl_xor_sync(0xffffffffu, sum, off);
        sq  += __shfl_xor_sync(0xffffffffu, sq,  off);
    }
    const int w = tid >> 5, lane = tid & 31;
    if (lane == 0) { red[0][w] = sum; red[1][w] = sq; }
    __syncthreads();
    if (tid == 0) {
        float s = 0.f, q = 0.f;
        #pragma unroll
        for (int i = 0; i < 8; i++) { s += red[0][i]; q += red[1][i]; }
        red[0][0] = s; red[1][0] = q;
    }
    __syncthreads();
    sum = red[0][0]; sq = red[1][0];

    float mean = sum / (float)DM_;
    float var  = (sq - (float)DM_ * mean * mean) / (float)(DM_ - 1);
    var = fmaxf(var, 0.f);
    float inv = 1.f / (sqrtf(var) + 1e-6f);

    float4 g4 = *(const float4*)(gamma + c);
    float4 b4 = *(const float4*)(beta + c);
    float4 ov;
    ov.x = g4.x * (xv.x - mean) * inv + b4.x;
    ov.y = g4.y * (xv.y - mean) * inv + b4.y;
    ov.z = g4.z * (xv.z - mean) * inv + b4.z;
    ov.w = g4.w * (xv.w - mean) * inv + b4.w;
    *(float4*)(out + (size_t)row * DM_ + c) = ov;
}

// ---------------------------------------------------------------------------
extern "C" void kernel_launch(void* const* d_in, const int* in_sizes, int n_in,
                              void* d_out, int out_size)
{
    (void)in_sizes; (void)n_in; (void)out_size;
    const float* query = (const float*)d_in[0];
    const float* key_  = (const float*)d_in[1];
    const float* value = (const float*)d_in[2];
    const int*   mask  = (const int*)  d_in[3];
    const float* Wq = (const float*)d_in[4];
    const float* bq = (const float*)d_in[5];
    const float* Wk = (const float*)d_in[6];
    const float* bk = (const float*)d_in[7];
    const float* Wv = (const float*)d_in[8];
    const float* bv = (const float*)d_in[9];
    const float* Wo = (const float*)d_in[10];
    const float* bo = (const float*)d_in[11];
    const float* gamma = (const float*)d_in[12];
    const float* beta  = (const float*)d_in[13];
    float* out = (float*)d_out;

    dim3 gg(DM_/128, MTOT/128);   // (8, 32)
    sgemm_nt<false><<<gg, 256>>>(query, Wq, bq, nullptr, 0, DM_);
    sgemm_nt<false><<<gg, 256>>>(key_,  Wk, bk, nullptr, 1, DM_);
    sgemm_nt<false><<<gg, 256>>>(value, Wv, bv, nullptr, 2, DM_);

    flash_attn<<<dim3(S_/64, B_*H_), 256>>>(mask);

    sgemm_nt<true><<<gg, 256>>>(nullptr, Wo, bo, query, 3, DM_);

    layernorm<<<MTOT, 256>>>(gamma, beta, out);
}

// round 4
// speedup vs baseline: 2.7078x; 2.7078x over previous
#include <cuda_runtime.h>
#include <math.h>

#define B_   2
#define S_   2048
#define DM_  1024
#define H_   16
#define HD_  64
#define MTOT (B_*S_)

// Scratch (alloc-free rule: __device__ globals)
__device__ float g_Q[MTOT*DM_];
__device__ float g_K[MTOT*DM_];
__device__ float g_V[MTOT*DM_];
__device__ float g_attn[MTOT*DM_];
__device__ float g_x[MTOT*DM_];

__device__ __forceinline__ unsigned f2tf(float f) {
    unsigned u; asm("cvt.rna.tf32.f32 %0, %1;" : "=r"(u) : "f"(f)); return u;
}

__device__ __forceinline__ void mma8(float* d, const unsigned* a, const unsigned* b, const float* c) {
    asm volatile("mma.sync.aligned.m16n8k8.row.col.f32.tf32.tf32.f32 "
        "{%0,%1,%2,%3}, {%4,%5,%6,%7}, {%8,%9}, {%10,%11,%12,%13};"
        : "=f"(d[0]), "=f"(d[1]), "=f"(d[2]), "=f"(d[3])
        : "r"(a[0]), "r"(a[1]), "r"(a[2]), "r"(a[3]),
          "r"(b[0]), "r"(b[1]),
          "f"(c[0]), "f"(c[1]), "f"(c[2]), "f"(c[3]));
}

// ---------------------------------------------------------------------------
// tf32 tensor-core GEMM (NT): C[m][n] = sum_k A[m][k]*W[n][k] + bias[n] (+res)
// 128x128 tile, BK=32, 256 threads (8 warps, 2x4), warp tile 64x32.
// smem stride 36 floats -> conflict-free fragment loads (banks 4g+t).
// ---------------------------------------------------------------------------
template<bool ADD_RES>
__global__ __launch_bounds__(256)
void tgemm(const float* __restrict__ A, const float* __restrict__ W,
           const float* __restrict__ bias, const float* __restrict__ res, int which)
{
    __shared__ unsigned As[128*36];
    __shared__ unsigned Bs[128*36];

    const float* Abase = (A == nullptr) ? (const float*)g_attn : A;
    float* C = ADD_RES ? g_x : (which == 0 ? g_Q : (which == 1 ? g_K : g_V));

    const int tid = threadIdx.x;
    const int warp = tid >> 5, lane = tid & 31;
    const int g = lane >> 2, t = lane & 3;
    const int wm = warp >> 2, wn = warp & 3;       // 2 x 4 warp grid
    const int m0 = blockIdx.y * 128, n0 = blockIdx.x * 128;

    float acc[4][4][4];
    #pragma unroll
    for (int mt = 0; mt < 4; mt++)
        #pragma unroll
        for (int nt = 0; nt < 4; nt++)
            #pragma unroll
            for (int i = 0; i < 4; i++) acc[mt][nt][i] = 0.f;

    for (int k0 = 0; k0 < DM_; k0 += 32) {
        __syncthreads();
        #pragma unroll
        for (int i = 0; i < 4; i++) {
            int idx = tid + i*256;
            int r = idx >> 3, c = (idx & 7) << 2;
            float4 a4 = *(const float4*)(Abase + (size_t)(m0 + r)*DM_ + k0 + c);
            float4 w4 = *(const float4*)(W     + (size_t)(n0 + r)*DM_ + k0 + c);
            uint4 at; at.x = f2tf(a4.x); at.y = f2tf(a4.y); at.z = f2tf(a4.z); at.w = f2tf(a4.w);
            uint4 wt; wt.x = f2tf(w4.x); wt.y = f2tf(w4.y); wt.z = f2tf(w4.z); wt.w = f2tf(w4.w);
            *(uint4*)&As[r*36 + c] = at;
            *(uint4*)&Bs[r*36 + c] = wt;
        }
        __syncthreads();

        #pragma unroll
        for (int ks = 0; ks < 4; ks++) {
            unsigned af[4][4], bf[4][2];
            #pragma unroll
            for (int mt = 0; mt < 4; mt++) {
                int base = (wm*64 + mt*16 + g)*36 + ks*8 + t;
                af[mt][0] = As[base];
                af[mt][1] = As[base + 8*36];
                af[mt][2] = As[base + 4];
                af[mt][3] = As[base + 8*36 + 4];
            }
            #pragma unroll
            for (int nt = 0; nt < 4; nt++) {
                int base = (wn*32 + nt*8 + g)*36 + ks*8 + t;
                bf[nt][0] = Bs[base];
                bf[nt][1] = Bs[base + 4];
            }
            #pragma unroll
            for (int mt = 0; mt < 4; mt++)
                #pragma unroll
                for (int nt = 0; nt < 4; nt++)
                    mma8(acc[mt][nt], af[mt], bf[nt], acc[mt][nt]);
        }
    }

    #pragma unroll
    for (int mt = 0; mt < 4; mt++) {
        int row = m0 + wm*64 + mt*16 + g;
        #pragma unroll
        for (int nt = 0; nt < 4; nt++) {
            int col = n0 + wn*32 + nt*8 + 2*t;
            float2 bv = *(const float2*)&bias[col];
            float v0 = acc[mt][nt][0] + bv.x, v1 = acc[mt][nt][1] + bv.y;
            float v2 = acc[mt][nt][2] + bv.x, v3 = acc[mt][nt][3] + bv.y;
            if (ADD_RES) {
                float2 r0 = *(const float2*)&res[(size_t)row*DM_ + col];
                float2 r1 = *(const float2*)&res[(size_t)(row+8)*DM_ + col];
                v0 += r0.x; v1 += r0.y; v2 += r1.x; v3 += r1.y;
            }
            *(float2*)&C[(size_t)row*DM_ + col]     = make_float2(v0, v1);
            *(float2*)&C[(size_t)(row+8)*DM_ + col] = make_float2(v2, v3);
        }
    }
}

// ---------------------------------------------------------------------------
// Flash attention with tf32 mma.sync.
// Block = 128 threads (4 warps), 64 query rows (16/warp). KV tiles of 64.
// smem: KP[64][68] (K tile, then reused as P tile), Vs[64][68]. ~34KB.
// Q held as register fragments, pre-scaled by 1/sqrt(64).
// ---------------------------------------------------------------------------
__global__ __launch_bounds__(128)
void flash_tc(const int* __restrict__ mask)
{
    __shared__ unsigned KP[64*68];
    __shared__ unsigned Vs[64*68];

    const int tid = threadIdx.x;
    const int warp = tid >> 5, lane = tid & 31;
    const int g = lane >> 2, t = lane & 3;
    const int q0 = blockIdx.x * 64;
    const int bh = blockIdx.y, b = bh >> 4, h = bh & 15;
    const int wq = warp * 16;
    const float scale = 0.125f;

    // Load Q tile into KP, extract fragments, then KP is free for K.
    {
        const float* src = g_Q + ((size_t)(b*S_ + q0))*DM_ + h*HD_;
        #pragma unroll
        for (int i = 0; i < 8; i++) {
            int idx = tid + i*128;
            int r = idx >> 4, c = (idx & 15) << 2;
            float4 v = *(const float4*)(src + (size_t)r*DM_ + c);
            uint4 u; u.x = f2tf(v.x*scale); u.y = f2tf(v.y*scale);
                     u.z = f2tf(v.z*scale); u.w = f2tf(v.w*scale);
            *(uint4*)&KP[r*68 + c] = u;
        }
    }
    __syncthreads();

    unsigned qf[8][4];
    #pragma unroll
    for (int ks = 0; ks < 8; ks++) {
        int base = (wq + g)*68 + ks*8 + t;
        qf[ks][0] = KP[base];
        qf[ks][1] = KP[base + 8*68];
        qf[ks][2] = KP[base + 4];
        qf[ks][3] = KP[base + 8*68 + 4];
    }

    float o[8][4];
    #pragma unroll
    for (int nt = 0; nt < 8; nt++)
        #pragma unroll
        for (int i = 0; i < 4; i++) o[nt][i] = 0.f;
    float mi[2] = {-1e30f, -1e30f}, li[2] = {0.f, 0.f};

    const int* mrow0 = mask + ((size_t)b*S_ + q0 + wq + g)*S_;
    const int* mrow1 = mrow0 + 8*S_;

    for (int k0 = 0; k0 < S_; k0 += 64) {
        __syncthreads();   // previous tile's PV done reading KP/Vs
        {
            const float* ksrc = g_K + ((size_t)(b*S_ + k0))*DM_ + h*HD_;
            const float* vsrc = g_V + ((size_t)(b*S_ + k0))*DM_ + h*HD_;
            #pragma unroll
            for (int i = 0; i < 8; i++) {
                int idx = tid + i*128;
                int r = idx >> 4, c = (idx & 15) << 2;
                float4 kv = *(const float4*)(ksrc + (size_t)r*DM_ + c);
                float4 vv = *(const float4*)(vsrc + (size_t)r*DM_ + c);
                uint4 ku; ku.x = f2tf(kv.x); ku.y = f2tf(kv.y); ku.z = f2tf(kv.z); ku.w = f2tf(kv.w);
                uint4 vu; vu.x = f2tf(vv.x); vu.y = f2tf(vv.y); vu.z = f2tf(vv.z); vu.w = f2tf(vv.w);
                *(uint4*)&KP[r*68 + c] = ku;
                *(uint4*)&Vs[r*68 + c] = vu;
            }
        }
        __syncthreads();

        // S = Q K^T
        float s[8][4];
        #pragma unroll
        for (int nt = 0; nt < 8; nt++)
            #pragma unroll
            for (int i = 0; i < 4; i++) s[nt][i] = 0.f;

        #pragma unroll
        for (int ks = 0; ks < 8; ks++) {
            #pragma unroll
            for (int nt = 0; nt < 8; nt++) {
                unsigned bf[2];
                int base = (nt*8 + g)*68 + ks*8 + t;
                bf[0] = KP[base];
                bf[1] = KP[base + 4];
                mma8(s[nt], qf[ks], bf, s[nt]);
            }
        }

        // Mask
        #pragma unroll
        for (int nt = 0; nt < 8; nt++) {
            int c = k0 + nt*8 + 2*t;
            int2 m0v = *(const int2*)&mrow0[c];
            int2 m1v = *(const int2*)&mrow1[c];
            if (m0v.x == 0) s[nt][0] = -1e9f;
            if (m0v.y == 0) s[nt][1] = -1e9f;
            if (m1v.x == 0) s[nt][2] = -1e9f;
            if (m1v.y == 0) s[nt][3] = -1e9f;
        }

        // Online softmax; row rr=0 -> frag slots 0,1 (row g); rr=1 -> 2,3 (row g+8)
        #pragma unroll
        for (int rr = 0; rr < 2; rr++) {
            float mx = -1e30f;
            #pragma unroll
            for (int nt = 0; nt < 8; nt++)
                mx = fmaxf(mx, fmaxf(s[nt][2*rr], s[nt][2*rr+1]));
            mx = fmaxf(mx, __shfl_xor_sync(0xffffffffu, mx, 1));
            mx = fmaxf(mx, __shfl_xor_sync(0xffffffffu, mx, 2));
            float mnew = fmaxf(mi[rr], mx);
            float alpha = __expf(mi[rr] - mnew);
            float sum = 0.f;
            #pragma unroll
            for (int nt = 0; nt < 8; nt++) {
                s[nt][2*rr]   = __expf(s[nt][2*rr]   - mnew);
                s[nt][2*rr+1] = __expf(s[nt][2*rr+1] - mnew);
                sum += s[nt][2*rr] + s[nt][2*rr+1];
            }
            sum += __shfl_xor_sync(0xffffffffu, sum, 1);
            sum += __shfl_xor_sync(0xffffffffu, sum, 2);
            li[rr] = li[rr]*alpha + sum;
            mi[rr] = mnew;
            #pragma unroll
            for (int nt = 0; nt < 8; nt++) {
                o[nt][2*rr]   *= alpha;
                o[nt][2*rr+1] *= alpha;
            }
        }

        __syncthreads();   // all warps done reading KP as K
        // Write P (tf32) into KP: P[q][key], stride 68
        #pragma unroll
        for (int nt = 0; nt < 8; nt++) {
            int base = (wq + g)*68 + nt*8 + 2*t;
            uint2 p0; p0.x = f2tf(s[nt][0]); p0.y = f2tf(s[nt][1]);
            uint2 p1; p1.x = f2tf(s[nt][2]); p1.y = f2tf(s[nt][3]);
            *(uint2*)&KP[base]        = p0;
            *(uint2*)&KP[base + 8*68] = p1;
        }
        __syncthreads();

        // O += P V
        #pragma unroll
        for (int ks = 0; ks < 8; ks++) {
            unsigned pa[4];
            int base = (wq + g)*68 + ks*8 + t;
            pa[0] = KP[base];
            pa[1] = KP[base + 8*68];
            pa[2] = KP[base + 4];
            pa[3] = KP[base + 8*68 + 4];
            #pragma unroll
            for (int nt = 0; nt < 8; nt++) {
                unsigned bf[2];
                bf[0] = Vs[(ks*8 + t)*68 + nt*8 + g];
                bf[1] = Vs[(ks*8 + t + 4)*68 + nt*8 + g];
                mma8(o[nt], pa, bf, o[nt]);
            }
        }
    }

    // Epilogue
    float inv0 = 1.f / li[0], inv1 = 1.f / li[1];
    float* dst0 = g_attn + ((size_t)(b*S_ + q0 + wq + g))*DM_ + h*HD_;
    float* dst1 = dst0 + (size_t)8*DM_;
    #pragma unroll
    for (int nt = 0; nt < 8; nt++) {
        int c = nt*8 + 2*t;
        *(float2*)&dst0[c] = make_float2(o[nt][0]*inv0, o[nt][1]*inv0);
        *(float2*)&dst1[c] = make_float2(o[nt][2]*inv1, o[nt][3]*inv1);
    }
}

// ---------------------------------------------------------------------------
// LayerNorm: unbiased std (ddof=1), denominator (std + eps). One block per row.
// ---------------------------------------------------------------------------
__global__ __launch_bounds__(256)
void layernorm(const float* __restrict__ gamma, const float* __restrict__ beta,
               float* __restrict__ out)
{
    __shared__ float red[2][8];
    const int row = blockIdx.x;
    const int tid = threadIdx.x;
    const float* xr = g_x + (size_t)row * DM_;
    const int c = tid * 4;

    float4 xv = *(const float4*)(xr + c);
    float sum = xv.x + xv.y + xv.z + xv.w;
    float sq  = xv.x*xv.x + xv.y*xv.y + xv.z*xv.z + xv.w*xv.w;

    #pragma unroll
    for (int off = 16; off > 0; off >>= 1) {
        sum += __shfl_xor_sync(0xffffffffu, sum, off);
        sq  += __shfl_xor_sync(0xffffffffu, sq,  off);
    }
    const int w = tid >> 5, lane = tid & 31;
    if (lane == 0) { red[0][w] = sum; red[1][w] = sq; }
    __syncthreads();
    if (tid == 0) {
        float s = 0.f, q = 0.f;
        #pragma unroll
        for (int i = 0; i < 8; i++) { s += red[0][i]; q += red[1][i]; }
        red[0][0] = s; red[1][0] = q;
    }
    __syncthreads();
    sum = red[0][0]; sq = red[1][0];

    float mean = sum / (float)DM_;
    float var  = (sq - (float)DM_ * mean * mean) / (float)(DM_ - 1);
    var = fmaxf(var, 0.f);
    float inv = 1.f / (sqrtf(var) + 1e-6f);

    float4 g4 = *(const float4*)(gamma + c);
    float4 b4 = *(const float4*)(beta + c);
    float4 ov;
    ov.x = g4.x * (xv.x - mean) * inv + b4.x;
    ov.y = g4.y * (xv.y - mean) * inv + b4.y;
    ov.z = g4.z * (xv.z - mean) * inv + b4.z;
    ov.w = g4.w * (xv.w - mean) * inv + b4.w;
    *(float4*)(out + (size_t)row * DM_ + c) = ov;
}

// ---------------------------------------------------------------------------
extern "C" void kernel_launch(void* const* d_in, const int* in_sizes, int n_in,
                              void* d_out, int out_size)
{
    (void)in_sizes; (void)n_in; (void)out_size;
    const float* query = (const float*)d_in[0];
    const float* key_  = (const float*)d_in[1];
    const float* value = (const float*)d_in[2];
    const int*   mask  = (const int*)  d_in[3];
    const float* Wq = (const float*)d_in[4];
    const float* bq = (const float*)d_in[5];
    const float* Wk = (const float*)d_in[6];
    const float* bk = (const float*)d_in[7];
    const float* Wv = (const float*)d_in[8];
    const float* bv = (const float*)d_in[9];
    const float* Wo = (const float*)d_in[10];
    const float* bo = (const float*)d_in[11];
    const float* gamma = (const float*)d_in[12];
    const float* beta  = (const float*)d_in[13];
    float* out = (float*)d_out;

    dim3 gg(DM_/128, MTOT/128);   // (8, 32)
    tgemm<false><<<gg, 256>>>(query, Wq, bq, nullptr, 0);
    tgemm<false><<<gg, 256>>>(key_,  Wk, bk, nullptr, 1);
    tgemm<false><<<gg, 256>>>(value, Wv, bv, nullptr, 2);

    flash_tc<<<dim3(S_/64, B_*H_), 128>>>(mask);

    tgemm<true><<<gg, 256>>>(nullptr, Wo, bo, query, 3);

    layernorm<<<MTOT, 256>>>(gamma, beta, out);
}